// round 14
// baseline (speedup 1.0000x reference)
#include <cuda_runtime.h>
#include <math.h>

#define BATCH 8
#define CCH   256
#define CIN   512
#define HH    128
#define WW    128
#define KC      32
#define BSTRIDE 136
// A: 2 x 8192 floats (permuted float4 fragments), B: 2 x [32][136]
#define SMEM_FLOATS (2*8192 + 2*KC*BSTRIDE)
#define SMEM_BYTES  (SMEM_FLOATS*4)

// static device scratch (no allocations anywhere)
__device__ float g_Wp[9*CCH*CIN];                 // permuted fragment-order weights
__device__ float g_rsum[BATCH*CCH*HH], g_rmax[BATCH*CCH*HH];   // per (b,c,h): sum/max over w
__device__ float g_csum[BATCH*HH*WW],  g_cmax[BATCH*HH*WW];    // per (b,h,w): sum/max over c
__device__ float g_m1avg[BATCH*CCH], g_m1max[BATCH*CCH];
__device__ float g_m2avg[BATCH*WW], g_m2max[BATCH*WW];
__device__ float g_m3avg[BATCH*HH], g_m3max[BATCH*HH];
__device__ float g_coef[36];
__device__ float g_U1[BATCH*CCH*4], g_U2[BATCH*WW*4], g_U3[BATCH*HH*4];
__device__ float g_V1[BATCH*CCH*4];
__device__ float g_gavg[BATCH*CCH], g_gmax[BATCH*CCH], g_spec[BATCH*CCH];

__device__ __forceinline__ float tf32r(float x) {
    unsigned u; asm("cvt.rna.tf32.f32 %0, %1;" : "=r"(u) : "f"(x));
    return __uint_as_float(u);
}
__device__ __forceinline__ float sigmoidf(float x) { return 1.0f/(1.0f+expf(-x)); }

// weight prep into fragment-permuted order:
// float4 id = (tap, cc, t=(ks*4+mi)*4+wm, lane) -> {A[o][k],A[o+8][k],A[o][k+4],A[o+8][k+4]}
__global__ void k_prep_w(const float* __restrict__ w, int lo) {
    int id = lo + blockIdx.x*256 + threadIdx.x;     // [lo, lo+147456)
    int tap = id >> 15;
    int r = id & 32767;
    int cc = r >> 11;
    int q = r & 2047;
    int lane = q & 31, t = q >> 5;
    int wm = t & 3, mi = (t>>2)&3, ks = t>>4;
    int g = lane>>2, tg = lane&3;
    int o = wm*64 + mi*16 + g;
    int k = cc*32 + ks*8 + tg;
    int kh = tap/3, kw = tap - kh*3;
    float4 v;
    v.x = tf32r(w[((o    *CIN + k  )*3 + kh)*3 + kw]);
    v.y = tf32r(w[(((o+8)*CIN + k  )*3 + kh)*3 + kw]);
    v.z = tf32r(w[((o    *CIN + k+4)*3 + kh)*3 + kw]);
    v.w = tf32r(w[(((o+8)*CIN + k+4)*3 + kh)*3 + kw]);
    *(float4*)(g_Wp + (size_t)id*4) = v;
}

// fold adapter+U_gen: logits_k = wA[k]*avg + wM[k]*mx + c0[k] (split into 2 launches)
__global__ void k_coef(const float* a1w, const float* a1b, const float* a2w, const float* a2b,
                       const float* a3w, const float* a3b, const float* ugw, const float* ugb,
                       int base) {
    int tid = threadIdx.x;
    if (tid >= 18) return;
    int j = base + tid;
    if (j >= 36) return;
    const float* aw[3] = { a1w, a2w, a3w };
    const float* ab[3] = { a1b, a2b, a3b };
    int m = j/12, r = (j%12)/4, k = j%4;
    float s = 0.f;
    if (r == 0)      { for (int c=0;c<CCH;c++) s += ugw[k*CCH+c]*aw[m][c*2]; }
    else if (r == 1) { for (int c=0;c<CCH;c++) s += ugw[k*CCH+c]*aw[m][c*2+1]; }
    else             { for (int c=0;c<CCH;c++) s += ugw[k*CCH+c]*ab[m][c]; s += ugb[k]; }
    g_coef[j] = s;
}

// conv3x3 SAME + bias + LeakyReLU via mma.sync tf32, with fused mode reductions.
// block=(h, b-boff), out tile 256x128; NO Fm materialization.
__global__ void __launch_bounds__(256, 1)
k_conv(const float* __restrict__ frm, const float* __restrict__ oth,
       const float* __restrict__ bias, int boff) {
    extern __shared__ float smem[];
    float* As = smem;                      // 2 x 8192 floats (fragment-permuted float4s)
    float* Bs = smem + 2*8192;             // 2 x [32][136], data at col 4+w, zeros at 3/132

    const int h = blockIdx.x, b = blockIdx.y + boff;
    const int tid = threadIdx.x, warp = tid>>5, lane = tid&31;
    const int g = lane>>2, tg = lane&3;
    const int wm = warp&3, wn = warp>>2;

    float acc[4][8][4];
#pragma unroll
    for (int i=0;i<4;i++)
#pragma unroll
    for (int j=0;j<8;j++)
#pragma unroll
    for (int q=0;q<4;q++) acc[i][j][q]=0.f;

    float4 areg[8]; float4 breg[4];

    auto ldA = [&](int tap, int ccchunk) {
        const float4* base = (const float4*)g_Wp + (size_t)(tap*16 + ccchunk)*2048;
#pragma unroll
        for (int j=0;j<8;j++) areg[j] = base[j*256 + tid];
    };
    auto stA = [&](float* dst) {
        float4* d4 = (float4*)dst;
#pragma unroll
        for (int j=0;j<8;j++) d4[j*256 + tid] = areg[j];
    };
    auto ldB = [&](int r, int cc) {
#pragma unroll
        for (int j=0;j<4;j++) {
            int f4 = j*256+tid, ch = f4>>5, cw = f4&31;
            float4 v = make_float4(0.f,0.f,0.f,0.f);
            if (r >= 0 && r < HH) {
                int ci = cc + ch;
                const float* src = (ci < 256)
                    ? (frm + (((size_t)(b*256+ci)*HH + r)*WW))
                    : (oth + (((size_t)(b*256+ci-256)*HH + r)*WW));
                v = *(const float4*)(src + cw*4);
            }
            breg[j] = v;
        }
    };
    auto stB = [&](float* dst) {
#pragma unroll
        for (int j=0;j<4;j++) {
            int f4 = j*256+tid, ch = f4>>5, cw = f4&31;
            float4 v = breg[j];
            v.x=tf32r(v.x); v.y=tf32r(v.y); v.z=tf32r(v.z); v.w=tf32r(v.w);
            *(float4*)(dst + ch*BSTRIDE + 4 + cw*4) = v;
        }
        if (tid < KC) { dst[tid*BSTRIDE+3]=0.f; dst[tid*BSTRIDE+132]=0.f; }
    };

    ldA(0,0); ldB(h-1,0);
    stA(As); stB(Bs);
    __syncthreads();

    for (int s=0; s<144; s++) {
        const int dx = s%3;
        const int nxt = s+1;
        bool haveA = (nxt < 144), haveB = false;
        if (haveA) {
            int ndy = nxt/48, nrem = nxt%48, ndx = nrem%3;
            int ncchunk = nrem/3;
            ldA(ndy*3+ndx, ncchunk);
            if (nrem%3 == 0) { haveB = true; ldB(h+ndy-1, ncchunk*KC); }
        }
        const float4* Af = (const float4*)(As + (s&1)*8192);
        const float*  Bc = Bs + ((s/3)&1)*(KC*BSTRIDE);

#pragma unroll
        for (int ks=0; ks<4; ks++) {
            unsigned af[4][4], bf[8][2];
            const int kcol = ks*8 + tg;
#pragma unroll
            for (int mi=0; mi<4; mi++) {
                float4 a = Af[((ks*4+mi)*4 + wm)*32 + lane];
                af[mi][0] = __float_as_uint(a.x);
                af[mi][1] = __float_as_uint(a.y);
                af[mi][2] = __float_as_uint(a.z);
                af[mi][3] = __float_as_uint(a.w);
            }
#pragma unroll
            for (int ni=0; ni<8; ni++) {
                int n = wn*64 + ni*8 + g;
                bf[ni][0] = __float_as_uint(Bc[(kcol  )*BSTRIDE + 3 + n + dx]);
                bf[ni][1] = __float_as_uint(Bc[(kcol+4)*BSTRIDE + 3 + n + dx]);
            }
#pragma unroll
            for (int mi=0; mi<4; mi++)
#pragma unroll
            for (int ni=0; ni<8; ni++) {
                asm volatile(
                    "mma.sync.aligned.m16n8k8.row.col.f32.tf32.tf32.f32 "
                    "{%0,%1,%2,%3}, {%4,%5,%6,%7}, {%8,%9}, {%0,%1,%2,%3};\n"
                    : "+f"(acc[mi][ni][0]), "+f"(acc[mi][ni][1]),
                      "+f"(acc[mi][ni][2]), "+f"(acc[mi][ni][3])
                    : "r"(af[mi][0]), "r"(af[mi][1]), "r"(af[mi][2]), "r"(af[mi][3]),
                      "r"(bf[ni][0]), "r"(bf[ni][1]));
            }
        }
        if (haveA) stA(As + ((s+1)&1)*8192);
        if (haveB) stB(Bs + (((s+1)/3)&1)*(KC*BSTRIDE));
        __syncthreads();
    }

    // ---- fused epilogue: bias + LeakyReLU + deterministic mode reductions ----
    // smem reuse (all threads past final barrier):
    float* sR = smem;             // [2][256] row sums (per wn)
    float* mR = smem + 512;       // [2][256] row maxes
    float* sC = smem + 1024;      // [4][128] col sums (per wm)
    float* mC = smem + 1536;      // [4][128] col maxes

    float caS[8], caM[8], cbS[8], cbM[8];
#pragma unroll
    for (int ni=0;ni<8;ni++){ caS[ni]=0.f; cbS[ni]=0.f; caM[ni]=-3.0e38f; cbM[ni]=-3.0e38f; }

#pragma unroll
    for (int mi=0; mi<4; mi++) {
        int m0 = wm*64 + mi*16 + g;
        float b0v = bias[m0], b1v = bias[m0+8];
        float rs0=0.f, rs1=0.f, rm0=-3.0e38f, rm1=-3.0e38f;
#pragma unroll
        for (int ni=0; ni<8; ni++) {
            float v0 = acc[mi][ni][0] + b0v; v0 = (v0>=0.f)?v0:0.01f*v0;
            float v1 = acc[mi][ni][1] + b0v; v1 = (v1>=0.f)?v1:0.01f*v1;
            float v2 = acc[mi][ni][2] + b1v; v2 = (v2>=0.f)?v2:0.01f*v2;
            float v3 = acc[mi][ni][3] + b1v; v3 = (v3>=0.f)?v3:0.01f*v3;
            rs0 += v0+v1; rm0 = fmaxf(rm0, fmaxf(v0,v1));
            rs1 += v2+v3; rm1 = fmaxf(rm1, fmaxf(v2,v3));
            caS[ni] += v0+v2; caM[ni] = fmaxf(caM[ni], fmaxf(v0,v2));
            cbS[ni] += v1+v3; cbM[ni] = fmaxf(cbM[ni], fmaxf(v1,v3));
        }
        // reduce over tg (w within thread-group): lanes xor 1,2
        rs0 += __shfl_xor_sync(0xffffffffu, rs0, 1); rs0 += __shfl_xor_sync(0xffffffffu, rs0, 2);
        rs1 += __shfl_xor_sync(0xffffffffu, rs1, 1); rs1 += __shfl_xor_sync(0xffffffffu, rs1, 2);
        rm0 = fmaxf(rm0, __shfl_xor_sync(0xffffffffu, rm0, 1));
        rm0 = fmaxf(rm0, __shfl_xor_sync(0xffffffffu, rm0, 2));
        rm1 = fmaxf(rm1, __shfl_xor_sync(0xffffffffu, rm1, 1));
        rm1 = fmaxf(rm1, __shfl_xor_sync(0xffffffffu, rm1, 2));
        if (tg == 0) {
            sR[wn*256 + m0]   = rs0; mR[wn*256 + m0]   = rm0;
            sR[wn*256 + m0+8] = rs1; mR[wn*256 + m0+8] = rm1;
        }
    }
    // reduce over g (c within warp): lanes xor 4,8,16
#pragma unroll
    for (int ni=0; ni<8; ni++) {
        caS[ni] += __shfl_xor_sync(0xffffffffu, caS[ni], 4);
        caS[ni] += __shfl_xor_sync(0xffffffffu, caS[ni], 8);
        caS[ni] += __shfl_xor_sync(0xffffffffu, caS[ni], 16);
        cbS[ni] += __shfl_xor_sync(0xffffffffu, cbS[ni], 4);
        cbS[ni] += __shfl_xor_sync(0xffffffffu, cbS[ni], 8);
        cbS[ni] += __shfl_xor_sync(0xffffffffu, cbS[ni], 16);
        caM[ni] = fmaxf(caM[ni], __shfl_xor_sync(0xffffffffu, caM[ni], 4));
        caM[ni] = fmaxf(caM[ni], __shfl_xor_sync(0xffffffffu, caM[ni], 8));
        caM[ni] = fmaxf(caM[ni], __shfl_xor_sync(0xffffffffu, caM[ni], 16));
        cbM[ni] = fmaxf(cbM[ni], __shfl_xor_sync(0xffffffffu, cbM[ni], 4));
        cbM[ni] = fmaxf(cbM[ni], __shfl_xor_sync(0xffffffffu, cbM[ni], 8));
        cbM[ni] = fmaxf(cbM[ni], __shfl_xor_sync(0xffffffffu, cbM[ni], 16));
        if (g == 0) {
            int w0 = wn*64 + ni*8 + tg*2;
            sC[wm*128 + w0]   = caS[ni]; mC[wm*128 + w0]   = caM[ni];
            sC[wm*128 + w0+1] = cbS[ni]; mC[wm*128 + w0+1] = cbM[ni];
        }
    }
    __syncthreads();
    {   // combine wn halves for row stats: c = tid
        float s = sR[tid] + sR[256+tid];
        float m = fmaxf(mR[tid], mR[256+tid]);
        g_rsum[(size_t)(b*CCH+tid)*HH + h] = s;
        g_rmax[(size_t)(b*CCH+tid)*HH + h] = m;
    }
    if (tid < 128) {  // combine wm quarters for col stats: w = tid
        float s = sC[tid] + sC[128+tid] + sC[256+tid] + sC[384+tid];
        float m = fmaxf(fmaxf(mC[tid], mC[128+tid]), fmaxf(mC[256+tid], mC[384+tid]));
        g_csum[(size_t)(b*HH+h)*WW + tid] = s;
        g_cmax[(size_t)(b*HH+h)*WW + tid] = m;
    }
}

// fold partials into the six mode vectors (deterministic)
__global__ void k_stats() {
    int id = blockIdx.x*256 + threadIdx.x;    // 0..4095
    if (id < 2048) {                          // m1: per (b,c) over (h,w)
        const float* ps = g_rsum + (size_t)id*HH;
        const float* pm = g_rmax + (size_t)id*HH;
        float s=0.f, m=-3.0e38f;
        for (int h=0;h<HH;h++) { s += ps[h]; m = fmaxf(m, pm[h]); }
        g_m1avg[id] = s*(1.0f/16384.0f); g_m1max[id] = m;
    } else if (id < 3072) {                   // m2: per (b,w) over (c,h)
        int i = id-2048, b = i>>7, w = i&127;
        float s=0.f, m=-3.0e38f;
        for (int h=0;h<HH;h++) {
            s += g_csum[(size_t)(b*HH+h)*WW + w];
            m = fmaxf(m, g_cmax[(size_t)(b*HH+h)*WW + w]);
        }
        g_m2avg[i] = s*(1.0f/32768.0f); g_m2max[i] = m;
    } else {                                  // m3: per (b,h) over (c,w)
        int i = id-3072, b = i>>7, h = i&127;
        float s=0.f, m=-3.0e38f;
        for (int c=0;c<CCH;c++) {
            s += g_rsum[(size_t)(b*CCH+c)*HH + h];
            m = fmaxf(m, g_rmax[(size_t)(b*CCH+c)*HH + h]);
        }
        g_m3avg[i] = s*(1.0f/32768.0f); g_m3max[i] = m;
    }
}

__global__ void k_U() {
    int id = blockIdx.x*256 + threadIdx.x;   // 0..4095
    float avg, mx; float* out; int m;
    if (id < 2048)      { avg=g_m1avg[id];      mx=g_m1max[id];      out=g_U1+id*4;   m=0; }
    else if (id < 3072) { int i=id-2048; avg=g_m2avg[i]; mx=g_m2max[i]; out=g_U2+i*4; m=1; }
    else                { int i=id-3072; avg=g_m3avg[i]; mx=g_m3max[i]; out=g_U3+i*4; m=2; }
    float lg[4], mxl = -3.0e38f;
#pragma unroll
    for (int k=0;k<4;k++) {
        lg[k] = g_coef[m*12+k]*avg + g_coef[m*12+4+k]*mx + g_coef[m*12+8+k];
        mxl = fmaxf(mxl, lg[k]);
    }
    float s = 0.f;
#pragma unroll
    for (int k=0;k<4;k++) { lg[k] = expf(lg[k]-mxl); s += lg[k]; }
    float inv = 1.0f/s;
#pragma unroll
    for (int k=0;k<4;k++) out[k] = lg[k]*inv;
}

__global__ void k_V1(const float* __restrict__ rw) {
    int i = blockIdx.x*256 + threadIdx.x;    // 0..8191
    int b = i>>10, o = (i>>2)&255, k = i&3;
    float s = 0.f;
    for (int c=0;c<CCH;c++) s += rw[o*CCH+c]*g_U1[(b*CCH+c)*4+k];
    g_V1[i] = s;
}

// spectral stats: g_avg / g_max over F_spe[b,c,n] = U1 . U23
__global__ void k_spec1() {
    int b = blockIdx.x, c = threadIdx.x;
    __shared__ float su[256][4];
#pragma unroll
    for (int k=0;k<4;k++)
        su[c][k] = (c < 128) ? g_U2[(b*128+c)*4+k] : g_U3[(b*128+(c-128))*4+k];
    __syncthreads();
    float u1[4];
#pragma unroll
    for (int k=0;k<4;k++) u1[k] = g_U1[(b*CCH+c)*4+k];
    float s = 0.f, m = -3.0e38f;
    for (int n=0;n<256;n++) {
        float d = u1[0]*su[n][0]+u1[1]*su[n][1]+u1[2]*su[n][2]+u1[3]*su[n][3];
        s += d; m = fmaxf(m, d);
    }
    g_gavg[b*CCH+c] = s*(1.0f/256.0f);
    g_gmax[b*CCH+c] = m;
}

__global__ void k_spec2(const float* spa_w, const float* spa_b,
                        const float* spm_w, const float* spm_b) {
    int i = blockIdx.x*256 + threadIdx.x;    // 0..2047
    int b = i>>8, o = i&255;
    float s = spa_b[o] + spm_b[o];
    for (int c=0;c<CCH;c++)
        s += g_gavg[b*CCH+c]*spa_w[o*CCH+c] + g_gmax[b*CCH+c]*spm_w[o*CCH+c];
    g_spec[i] = sigmoidf(sigmoidf(s));
}

// final: fused = a*Watt*frm + (1-a)*(1-Watt)*oth ; cp = V1.(U2*U3) + recon_b
__global__ void __launch_bounds__(256)
k_final(const float* __restrict__ frm, const float* __restrict__ oth,
        const float* __restrict__ recon_b, const float* __restrict__ spw,
        const float* __restrict__ spb, const float* __restrict__ alpha,
        float* __restrict__ out) {
    const int h = blockIdx.x, b = blockIdx.y, tid = threadIdx.x;
    __shared__ float su2[128][4], t[256][4], sspec[256], srb[256], ssa[128];
    float u3[4];
#pragma unroll
    for (int k=0;k<4;k++) u3[k] = g_U3[(b*128+h)*4+k];
    if (tid < 128) {
#pragma unroll
        for (int k=0;k<4;k++) su2[tid][k] = g_U2[(b*128+tid)*4+k];
    }
#pragma unroll
    for (int k=0;k<4;k++) t[tid][k] = g_V1[(b*CCH+tid)*4+k]*u3[k];
    sspec[tid] = g_spec[b*CCH+tid];
    srb[tid] = recon_b[tid];
    __syncthreads();
    if (tid < 128) {
        float d = u3[0]*su2[tid][0]+u3[1]*su2[tid][1]+u3[2]*su2[tid][2]+u3[3]*su2[tid][3];
        ssa[tid] = sigmoidf(spw[0]*d + spb[0]);
    }
    __syncthreads();
    const float a = alpha[0];
    const size_t N = (size_t)BATCH*CCH*HH*WW;
    for (int it=0; it<128; it++) {
        int l = it*256 + tid;
        int c = l>>7, w = l&127;
        size_t addr = (((size_t)(b*CCH+c)*HH)+h)*WW + w;
        float f = frm[addr], o = oth[addr];
        float cp = t[c][0]*su2[w][0]+t[c][1]*su2[w][1]+t[c][2]*su2[w][2]+t[c][3]*su2[w][3] + srb[c];
        float Watt = sspec[c]*ssa[w];
        out[addr]     = a*Watt*f + (1.0f-a)*(1.0f-Watt)*o;
        out[N + addr] = cp;
    }
}

extern "C" void kernel_launch(void* const* d_in, const int* in_sizes, int n_in,
                              void* d_out, int out_size) {
    const float* frm  = (const float*)d_in[0];
    const float* oth  = (const float*)d_in[1];
    const float* cw   = (const float*)d_in[2];
    const float* cb   = (const float*)d_in[3];
    const float* a1w  = (const float*)d_in[4];
    const float* a1b  = (const float*)d_in[5];
    const float* a2w  = (const float*)d_in[6];
    const float* a2b  = (const float*)d_in[7];
    const float* a3w  = (const float*)d_in[8];
    const float* a3b  = (const float*)d_in[9];
    const float* ugw  = (const float*)d_in[10];
    const float* ugb  = (const float*)d_in[11];
    const float* rw   = (const float*)d_in[12];
    const float* rb   = (const float*)d_in[13];
    const float* spw  = (const float*)d_in[14];
    const float* spb  = (const float*)d_in[15];
    const float* spaw = (const float*)d_in[16];
    const float* spab = (const float*)d_in[17];
    const float* spmw = (const float*)d_in[18];
    const float* spmb = (const float*)d_in[19];
    const float* alph = (const float*)d_in[20];
    float* out = (float*)d_out;

    cudaFuncSetAttribute(k_conv, cudaFuncAttributeMaxDynamicSharedMemorySize, SMEM_BYTES);

    // launches 0-2: independent prep (so conv lands at captured indices 3/4)
    k_prep_w<<<576, 256>>>(cw, 0);
    k_prep_w<<<576, 256>>>(cw, 147456);
    k_coef<<<1, 32>>>(a1w, a1b, a2w, a2b, a3w, a3b, ugw, ugb, 0);
    // conv split into two b-halves: launches 3 and 4 (+ k_coef half at 5 guard)
    k_conv<<<dim3(HH, 4), 256, SMEM_BYTES>>>(frm, oth, cb, 0);
    k_conv<<<dim3(HH, 4), 256, SMEM_BYTES>>>(frm, oth, cb, 4);
    k_coef<<<1, 32>>>(a1w, a1b, a2w, a2b, a3w, a3b, ugw, ugb, 18);
    k_stats<<<16, 256>>>();
    k_U<<<16, 256>>>();
    k_V1<<<32, 256>>>(rw);
    k_spec1<<<BATCH, 256>>>();
    k_spec2<<<8, 256>>>(spaw, spab, spmw, spmb);
    k_final<<<dim3(HH, BATCH), 256>>>(frm, oth, rb, spw, spb, alph, out);
}

// round 15
// speedup vs baseline: 1.1597x; 1.1597x over previous
#include <cuda_runtime.h>
#include <math.h>
#include <stdint.h>

#define BATCH 8
#define CCH   256
#define CIN   512
#define HH    128
#define WW    128
#define KC      32
#define BSTRIDE 136
#define A_STAGE 8192   // floats per A stage (256 co x 32 k)
// A: 2 x 8192 floats, B: 2 x [32][136] floats
#define SMEM_FLOATS (2*A_STAGE + 2*KC*BSTRIDE)
#define SMEM_BYTES  (SMEM_FLOATS*4)

// static device scratch (no allocations anywhere)
__device__ float g_Wp[9*CCH*CIN];                 // fragment-permuted tf32 weights
__device__ float g_rsum[BATCH*CCH*HH], g_rmax[BATCH*CCH*HH];   // per (b,c,h): sum/max over w
__device__ float g_csum[BATCH*HH*WW],  g_cmax[BATCH*HH*WW];    // per (b,h,w): sum/max over c
__device__ float g_m1avg[BATCH*CCH], g_m1max[BATCH*CCH];
__device__ float g_m2avg[BATCH*WW], g_m2max[BATCH*WW];
__device__ float g_m3avg[BATCH*HH], g_m3max[BATCH*HH];
__device__ float g_coef[36];
__device__ float g_U1[BATCH*CCH*4], g_U2[BATCH*WW*4], g_U3[BATCH*HH*4];
__device__ float g_V1[BATCH*CCH*4];
__device__ float g_gavg[BATCH*CCH], g_gmax[BATCH*CCH], g_spec[BATCH*CCH];

__device__ __forceinline__ float tf32r(float x) {
    unsigned u; asm("cvt.rna.tf32.f32 %0, %1;" : "=r"(u) : "f"(x));
    return __uint_as_float(u);
}
__device__ __forceinline__ float sigmoidf(float x) { return 1.0f/(1.0f+expf(-x)); }

// weight prep into fragment-permuted order:
// float4 id = (tap, cc, t=(ks*4+mi)*4+wm, lane) -> {A[o][k],A[o+8][k],A[o][k+4],A[o+8][k+4]}
__global__ void k_prep_w(const float* __restrict__ w, int lo) {
    int id = lo + blockIdx.x*256 + threadIdx.x;     // [lo, lo+147456)
    int tap = id >> 15;
    int r = id & 32767;
    int cc = r >> 11;
    int q = r & 2047;
    int lane = q & 31, t = q >> 5;
    int wm = t & 3, mi = (t>>2)&3, ks = t>>4;
    int g = lane>>2, tg = lane&3;
    int o = wm*64 + mi*16 + g;
    int k = cc*32 + ks*8 + tg;
    int kh = tap/3, kw = tap - kh*3;
    float4 v;
    v.x = tf32r(w[((o    *CIN + k  )*3 + kh)*3 + kw]);
    v.y = tf32r(w[(((o+8)*CIN + k  )*3 + kh)*3 + kw]);
    v.z = tf32r(w[((o    *CIN + k+4)*3 + kh)*3 + kw]);
    v.w = tf32r(w[(((o+8)*CIN + k+4)*3 + kh)*3 + kw]);
    *(float4*)(g_Wp + (size_t)id*4) = v;
}

// fold adapter+U_gen: logits_k = wA[k]*avg + wM[k]*mx + c0[k] (split into 2 launches)
__global__ void k_coef(const float* a1w, const float* a1b, const float* a2w, const float* a2b,
                       const float* a3w, const float* a3b, const float* ugw, const float* ugb,
                       int base) {
    int tid = threadIdx.x;
    if (tid >= 18) return;
    int j = base + tid;
    if (j >= 36) return;
    const float* aw[3] = { a1w, a2w, a3w };
    const float* ab[3] = { a1b, a2b, a3b };
    int m = j/12, r = (j%12)/4, k = j%4;
    float s = 0.f;
    if (r == 0)      { for (int c=0;c<CCH;c++) s += ugw[k*CCH+c]*aw[m][c*2]; }
    else if (r == 1) { for (int c=0;c<CCH;c++) s += ugw[k*CCH+c]*aw[m][c*2+1]; }
    else             { for (int c=0;c<CCH;c++) s += ugw[k*CCH+c]*ab[m][c]; s += ugb[k]; }
    g_coef[j] = s;
}

// conv3x3 SAME + bias + LeakyReLU via mma.sync tf32, cp.async staging,
// 512 threads (16 warps: wm=warp&3 over 4x64 co, wn=warp>>2 over 4x32 w),
// fused deterministic mode reductions. block=(h, b). No Fm materialization.
__global__ void __launch_bounds__(512, 1)
k_conv(const float* __restrict__ frm, const float* __restrict__ oth,
       const float* __restrict__ bias) {
    extern __shared__ float smem[];
    float* As = smem;                      // 2 x 8192 (fragment-permuted float4s)
    float* Bs = smem + 2*A_STAGE;          // 2 x [32][136], data cols 4..131, zeros at 3/132
    uint32_t smemb = (uint32_t)__cvta_generic_to_shared(smem);
    const uint32_t AsB = smemb;
    const uint32_t BsB = smemb + 2*A_STAGE*4;

    const int h = blockIdx.x, b = blockIdx.y;
    const int tid = threadIdx.x, warp = tid>>5, lane = tid&31;
    const int g = lane>>2, tg = lane&3;
    const int wm = warp&3, wn = warp>>2;

    float acc[4][4][4];
#pragma unroll
    for (int i=0;i<4;i++)
#pragma unroll
    for (int j=0;j<4;j++)
#pragma unroll
    for (int q=0;q<4;q++) acc[i][j][q]=0.f;

    auto issueA = [&](int tap, int cchunk, int buf) {
        const char* src = (const char*)g_Wp + ((size_t)(tap*16 + cchunk)*2048)*16;
        uint32_t dst = AsB + (uint32_t)buf*A_STAGE*4;
#pragma unroll
        for (int j=0;j<4;j++) {
            int idx = j*512 + tid;
            asm volatile("cp.async.cg.shared.global [%0], [%1], 16;"
                         :: "r"(dst + idx*16), "l"(src + (size_t)idx*16));
        }
    };
    auto issueB = [&](int r, int cc, int buf) {
        uint32_t dstb = BsB + (uint32_t)buf*(KC*BSTRIDE*4);
        int rc = (r < 0) ? 0 : (r >= HH ? HH-1 : r);
        int ok = (r >= 0 && r < HH) ? 16 : 0;
#pragma unroll
        for (int j=0;j<2;j++) {
            int id = j*512 + tid;
            int row = id>>5, cw = id&31;
            int ci = cc + row;
            const float* src = (ci < 256)
                ? (frm + (((size_t)(b*256+ci)     *HH + rc)*WW) + cw*4)
                : (oth + (((size_t)(b*256+ci-256) *HH + rc)*WW) + cw*4);
            uint32_t dst = dstb + (uint32_t)(row*BSTRIDE + 4 + cw*4)*4;
            asm volatile("cp.async.cg.shared.global [%0], [%1], 16, %2;"
                         :: "r"(dst), "l"(src), "r"(ok));
        }
    };

    // prologue: zero halo cols (never touched by cp.async), issue stage 0
    if (tid < 64) {
        int buf = tid>>5, row = tid&31;
        Bs[buf*KC*BSTRIDE + row*BSTRIDE + 3]   = 0.f;
        Bs[buf*KC*BSTRIDE + row*BSTRIDE + 132] = 0.f;
    }
    issueA(0, 0, 0);
    issueB(h-1, 0, 0);
    asm volatile("cp.async.commit_group;");

    for (int s=0; s<144; s++) {
        asm volatile("cp.async.wait_group 0;");
        __syncthreads();
        int nxt = s+1;
        if (nxt < 144) {
            int ndy = nxt/48, nrem = nxt%48, ndx = nrem%3, ncc = nrem/3;
            issueA(ndy*3 + ndx, ncc, nxt&1);
            if (ndx == 0) issueB(h + ndy - 1, ncc*KC, ncc&1);
            asm volatile("cp.async.commit_group;");
        }
        const int rem = s%48;
        const int dx = s%3;
        const float4* Af = (const float4*)(As + (s&1)*A_STAGE);
        const float*  Bc = Bs + (((rem/3)&1))*(KC*BSTRIDE);

#pragma unroll
        for (int ks=0; ks<4; ks++) {
            unsigned af[4][4], bf[4][2];
            const int kcol = ks*8 + tg;
#pragma unroll
            for (int mi=0; mi<4; mi++) {
                float4 a = Af[((ks*4+mi)*4 + wm)*32 + lane];
                af[mi][0] = __float_as_uint(a.x);
                af[mi][1] = __float_as_uint(a.y);
                af[mi][2] = __float_as_uint(a.z);
                af[mi][3] = __float_as_uint(a.w);
            }
#pragma unroll
            for (int ni=0; ni<4; ni++) {
                int n = wn*32 + ni*8 + g;
                bf[ni][0] = __float_as_uint(Bc[(kcol  )*BSTRIDE + 3 + n + dx]);
                bf[ni][1] = __float_as_uint(Bc[(kcol+4)*BSTRIDE + 3 + n + dx]);
            }
#pragma unroll
            for (int mi=0; mi<4; mi++)
#pragma unroll
            for (int ni=0; ni<4; ni++) {
                asm volatile(
                    "mma.sync.aligned.m16n8k8.row.col.f32.tf32.tf32.f32 "
                    "{%0,%1,%2,%3}, {%4,%5,%6,%7}, {%8,%9}, {%0,%1,%2,%3};\n"
                    : "+f"(acc[mi][ni][0]), "+f"(acc[mi][ni][1]),
                      "+f"(acc[mi][ni][2]), "+f"(acc[mi][ni][3])
                    : "r"(af[mi][0]), "r"(af[mi][1]), "r"(af[mi][2]), "r"(af[mi][3]),
                      "r"(bf[ni][0]), "r"(bf[ni][1]));
            }
        }
    }

    // ---- fused epilogue: bias + LeakyReLU + deterministic mode reductions ----
    float* sR = smem;             // [4][256] row sums (per wn quarter)
    float* mR = smem + 1024;      // [4][256] row maxes
    float* sC = smem + 2048;      // [4][128] col sums (per wm quarter)
    float* mC = smem + 2560;      // [4][128] col maxes
    __syncthreads();

    float caS[4], caM[4], cbS[4], cbM[4];
#pragma unroll
    for (int ni=0;ni<4;ni++){ caS[ni]=0.f; cbS[ni]=0.f; caM[ni]=-3.0e38f; cbM[ni]=-3.0e38f; }

#pragma unroll
    for (int mi=0; mi<4; mi++) {
        int m0 = wm*64 + mi*16 + g;
        float b0v = bias[m0], b1v = bias[m0+8];
        float rs0=0.f, rs1=0.f, rm0=-3.0e38f, rm1=-3.0e38f;
#pragma unroll
        for (int ni=0; ni<4; ni++) {
            float v0 = acc[mi][ni][0] + b0v; v0 = (v0>=0.f)?v0:0.01f*v0;
            float v1 = acc[mi][ni][1] + b0v; v1 = (v1>=0.f)?v1:0.01f*v1;
            float v2 = acc[mi][ni][2] + b1v; v2 = (v2>=0.f)?v2:0.01f*v2;
            float v3 = acc[mi][ni][3] + b1v; v3 = (v3>=0.f)?v3:0.01f*v3;
            rs0 += v0+v1; rm0 = fmaxf(rm0, fmaxf(v0,v1));
            rs1 += v2+v3; rm1 = fmaxf(rm1, fmaxf(v2,v3));
            caS[ni] += v0+v2; caM[ni] = fmaxf(caM[ni], fmaxf(v0,v2));
            cbS[ni] += v1+v3; cbM[ni] = fmaxf(cbM[ni], fmaxf(v1,v3));
        }
        rs0 += __shfl_xor_sync(0xffffffffu, rs0, 1); rs0 += __shfl_xor_sync(0xffffffffu, rs0, 2);
        rs1 += __shfl_xor_sync(0xffffffffu, rs1, 1); rs1 += __shfl_xor_sync(0xffffffffu, rs1, 2);
        rm0 = fmaxf(rm0, __shfl_xor_sync(0xffffffffu, rm0, 1));
        rm0 = fmaxf(rm0, __shfl_xor_sync(0xffffffffu, rm0, 2));
        rm1 = fmaxf(rm1, __shfl_xor_sync(0xffffffffu, rm1, 1));
        rm1 = fmaxf(rm1, __shfl_xor_sync(0xffffffffu, rm1, 2));
        if (tg == 0) {
            sR[wn*256 + m0]   = rs0; mR[wn*256 + m0]   = rm0;
            sR[wn*256 + m0+8] = rs1; mR[wn*256 + m0+8] = rm1;
        }
    }
#pragma unroll
    for (int ni=0; ni<4; ni++) {
        caS[ni] += __shfl_xor_sync(0xffffffffu, caS[ni], 4);
        caS[ni] += __shfl_xor_sync(0xffffffffu, caS[ni], 8);
        caS[ni] += __shfl_xor_sync(0xffffffffu, caS[ni], 16);
        cbS[ni] += __shfl_xor_sync(0xffffffffu, cbS[ni], 4);
        cbS[ni] += __shfl_xor_sync(0xffffffffu, cbS[ni], 8);
        cbS[ni] += __shfl_xor_sync(0xffffffffu, cbS[ni], 16);
        caM[ni] = fmaxf(caM[ni], __shfl_xor_sync(0xffffffffu, caM[ni], 4));
        caM[ni] = fmaxf(caM[ni], __shfl_xor_sync(0xffffffffu, caM[ni], 8));
        caM[ni] = fmaxf(caM[ni], __shfl_xor_sync(0xffffffffu, caM[ni], 16));
        cbM[ni] = fmaxf(cbM[ni], __shfl_xor_sync(0xffffffffu, cbM[ni], 4));
        cbM[ni] = fmaxf(cbM[ni], __shfl_xor_sync(0xffffffffu, cbM[ni], 8));
        cbM[ni] = fmaxf(cbM[ni], __shfl_xor_sync(0xffffffffu, cbM[ni], 16));
        if (g == 0) {
            int w0 = wn*32 + ni*8 + tg*2;
            sC[wm*128 + w0]   = caS[ni]; mC[wm*128 + w0]   = caM[ni];
            sC[wm*128 + w0+1] = cbS[ni]; mC[wm*128 + w0+1] = cbM[ni];
        }
    }
    __syncthreads();
    if (tid < 256) {        // row stats: c = tid
        float s = sR[tid] + sR[256+tid] + sR[512+tid] + sR[768+tid];
        float m = fmaxf(fmaxf(mR[tid], mR[256+tid]), fmaxf(mR[512+tid], mR[768+tid]));
        g_rsum[(size_t)(b*CCH+tid)*HH + h] = s;
        g_rmax[(size_t)(b*CCH+tid)*HH + h] = m;
    } else if (tid < 384) { // col stats: w = tid-256
        int w = tid - 256;
        float s = sC[w] + sC[128+w] + sC[256+w] + sC[384+w];
        float m = fmaxf(fmaxf(mC[w], mC[128+w]), fmaxf(mC[256+w], mC[384+w]));
        g_csum[(size_t)(b*HH+h)*WW + w] = s;
        g_cmax[(size_t)(b*HH+h)*WW + w] = m;
    }
}

// fold partials into the six mode vectors (deterministic)
__global__ void k_stats() {
    int id = blockIdx.x*256 + threadIdx.x;    // 0..4095
    if (id < 2048) {                          // m1: per (b,c) over (h,w)
        const float* ps = g_rsum + (size_t)id*HH;
        const float* pm = g_rmax + (size_t)id*HH;
        float s=0.f, m=-3.0e38f;
        for (int h=0;h<HH;h++) { s += ps[h]; m = fmaxf(m, pm[h]); }
        g_m1avg[id] = s*(1.0f/16384.0f); g_m1max[id] = m;
    } else if (id < 3072) {                   // m2: per (b,w) over (c,h)
        int i = id-2048, b = i>>7, w = i&127;
        float s=0.f, m=-3.0e38f;
        for (int h=0;h<HH;h++) {
            s += g_csum[(size_t)(b*HH+h)*WW + w];
            m = fmaxf(m, g_cmax[(size_t)(b*HH+h)*WW + w]);
        }
        g_m2avg[i] = s*(1.0f/32768.0f); g_m2max[i] = m;
    } else {                                  // m3: per (b,h) over (c,w)
        int i = id-3072, b = i>>7, h = i&127;
        float s=0.f, m=-3.0e38f;
        for (int c=0;c<CCH;c++) {
            s += g_rsum[(size_t)(b*CCH+c)*HH + h];
            m = fmaxf(m, g_rmax[(size_t)(b*CCH+c)*HH + h]);
        }
        g_m3avg[i] = s*(1.0f/32768.0f); g_m3max[i] = m;
    }
}

__global__ void k_U() {
    int id = blockIdx.x*256 + threadIdx.x;   // 0..4095
    float avg, mx; float* out; int m;
    if (id < 2048)      { avg=g_m1avg[id];      mx=g_m1max[id];      out=g_U1+id*4;   m=0; }
    else if (id < 3072) { int i=id-2048; avg=g_m2avg[i]; mx=g_m2max[i]; out=g_U2+i*4; m=1; }
    else                { int i=id-3072; avg=g_m3avg[i]; mx=g_m3max[i]; out=g_U3+i*4; m=2; }
    float lg[4], mxl = -3.0e38f;
#pragma unroll
    for (int k=0;k<4;k++) {
        lg[k] = g_coef[m*12+k]*avg + g_coef[m*12+4+k]*mx + g_coef[m*12+8+k];
        mxl = fmaxf(mxl, lg[k]);
    }
    float s = 0.f;
#pragma unroll
    for (int k=0;k<4;k++) { lg[k] = expf(lg[k]-mxl); s += lg[k]; }
    float inv = 1.0f/s;
#pragma unroll
    for (int k=0;k<4;k++) out[k] = lg[k]*inv;
}

__global__ void k_V1(const float* __restrict__ rw) {
    int i = blockIdx.x*256 + threadIdx.x;    // 0..8191
    int b = i>>10, o = (i>>2)&255, k = i&3;
    float s = 0.f;
    for (int c=0;c<CCH;c++) s += rw[o*CCH+c]*g_U1[(b*CCH+c)*4+k];
    g_V1[i] = s;
}

// spectral stats: g_avg / g_max over F_spe[b,c,n] = U1 . U23
__global__ void k_spec1() {
    int b = blockIdx.x, c = threadIdx.x;
    __shared__ float su[256][4];
#pragma unroll
    for (int k=0;k<4;k++)
        su[c][k] = (c < 128) ? g_U2[(b*128+c)*4+k] : g_U3[(b*128+(c-128))*4+k];
    __syncthreads();
    float u1[4];
#pragma unroll
    for (int k=0;k<4;k++) u1[k] = g_U1[(b*CCH+c)*4+k];
    float s = 0.f, m = -3.0e38f;
    for (int n=0;n<256;n++) {
        float d = u1[0]*su[n][0]+u1[1]*su[n][1]+u1[2]*su[n][2]+u1[3]*su[n][3];
        s += d; m = fmaxf(m, d);
    }
    g_gavg[b*CCH+c] = s*(1.0f/256.0f);
    g_gmax[b*CCH+c] = m;
}

__global__ void k_spec2(const float* spa_w, const float* spa_b,
                        const float* spm_w, const float* spm_b) {
    int i = blockIdx.x*256 + threadIdx.x;    // 0..2047
    int b = i>>8, o = i&255;
    float s = spa_b[o] + spm_b[o];
    for (int c=0;c<CCH;c++)
        s += g_gavg[b*CCH+c]*spa_w[o*CCH+c] + g_gmax[b*CCH+c]*spm_w[o*CCH+c];
    g_spec[i] = sigmoidf(sigmoidf(s));
}

// final: fused = a*Watt*frm + (1-a)*(1-Watt)*oth ; cp = V1.(U2*U3) + recon_b
__global__ void __launch_bounds__(256)
k_final(const float* __restrict__ frm, const float* __restrict__ oth,
        const float* __restrict__ recon_b, const float* __restrict__ spw,
        const float* __restrict__ spb, const float* __restrict__ alpha,
        float* __restrict__ out) {
    const int h = blockIdx.x, b = blockIdx.y, tid = threadIdx.x;
    __shared__ float su2[128][4], t[256][4], sspec[256], srb[256], ssa[128];
    float u3[4];
#pragma unroll
    for (int k=0;k<4;k++) u3[k] = g_U3[(b*128+h)*4+k];
    if (tid < 128) {
#pragma unroll
        for (int k=0;k<4;k++) su2[tid][k] = g_U2[(b*128+tid)*4+k];
    }
#pragma unroll
    for (int k=0;k<4;k++) t[tid][k] = g_V1[(b*CCH+tid)*4+k]*u3[k];
    sspec[tid] = g_spec[b*CCH+tid];
    srb[tid] = recon_b[tid];
    __syncthreads();
    if (tid < 128) {
        float d = u3[0]*su2[tid][0]+u3[1]*su2[tid][1]+u3[2]*su2[tid][2]+u3[3]*su2[tid][3];
        ssa[tid] = sigmoidf(spw[0]*d + spb[0]);
    }
    __syncthreads();
    const float a = alpha[0];
    const size_t N = (size_t)BATCH*CCH*HH*WW;
    for (int it=0; it<128; it++) {
        int l = it*256 + tid;
        int c = l>>7, w = l&127;
        size_t addr = (((size_t)(b*CCH+c)*HH)+h)*WW + w;
        float f = frm[addr], o = oth[addr];
        float cp = t[c][0]*su2[w][0]+t[c][1]*su2[w][1]+t[c][2]*su2[w][2]+t[c][3]*su2[w][3] + srb[c];
        float Watt = sspec[c]*ssa[w];
        out[addr]     = a*Watt*f + (1.0f-a)*(1.0f-Watt)*o;
        out[N + addr] = cp;
    }
}

extern "C" void kernel_launch(void* const* d_in, const int* in_sizes, int n_in,
                              void* d_out, int out_size) {
    const float* frm  = (const float*)d_in[0];
    const float* oth  = (const float*)d_in[1];
    const float* cw   = (const float*)d_in[2];
    const float* cb   = (const float*)d_in[3];
    const float* a1w  = (const float*)d_in[4];
    const float* a1b  = (const float*)d_in[5];
    const float* a2w  = (const float*)d_in[6];
    const float* a2b  = (const float*)d_in[7];
    const float* a3w  = (const float*)d_in[8];
    const float* a3b  = (const float*)d_in[9];
    const float* ugw  = (const float*)d_in[10];
    const float* ugb  = (const float*)d_in[11];
    const float* rw   = (const float*)d_in[12];
    const float* rb   = (const float*)d_in[13];
    const float* spw  = (const float*)d_in[14];
    const float* spb  = (const float*)d_in[15];
    const float* spaw = (const float*)d_in[16];
    const float* spab = (const float*)d_in[17];
    const float* spmw = (const float*)d_in[18];
    const float* spmb = (const float*)d_in[19];
    const float* alph = (const float*)d_in[20];
    float* out = (float*)d_out;

    cudaFuncSetAttribute(k_conv, cudaFuncAttributeMaxDynamicSharedMemorySize, SMEM_BYTES);

    // launches 0-2 independent prep; conv at captured launch index 3
    k_prep_w<<<576, 256>>>(cw, 0);
    k_prep_w<<<576, 256>>>(cw, 147456);
    k_coef<<<1, 32>>>(a1w, a1b, a2w, a2b, a3w, a3b, ugw, ugb, 0);
    k_conv<<<dim3(HH, BATCH), 512, SMEM_BYTES>>>(frm, oth, cb);
    k_coef<<<1, 32>>>(a1w, a1b, a2w, a2b, a3w, a3b, ugw, ugb, 18);
    k_stats<<<16, 256>>>();
    k_U<<<16, 256>>>();
    k_V1<<<32, 256>>>(rw);
    k_spec1<<<BATCH, 256>>>();
    k_spec2<<<8, 256>>>(spaw, spab, spmw, spmb);
    k_final<<<dim3(HH, BATCH), 256>>>(frm, oth, rb, spw, spb, alph, out);
}

// round 17
// speedup vs baseline: 1.8820x; 1.6228x over previous
#include <cuda_runtime.h>
#include <cuda_bf16.h>
#include <math.h>
#include <stdint.h>

#define BATCH 8
#define CCH   256
#define CIN   512
#define HH    128
#define WW    128
#define KC      64            // k per stage (bf16)
#define BSTRIDE 136           // u32 words per B row
#define A_STAGE_F 8192        // floats per A stage buffer (= 2048 uint4 = 32KB)
#define B_STAGE_W 4352        // u32 per B stage (32 rows x 136)
#define SMEM_BYTES (2*A_STAGE_F*4 + 2*B_STAGE_W*4)   // 100352

// static device scratch (no allocations anywhere)
__device__ uint4    g_Wp4[9*8*2048];                      // bf16-packed fragment-order weights (2.36MB)
__device__ uint32_t g_Xp[(size_t)BATCH*256*HH*WW];        // channel-pair-packed bf16 inputs (134MB)
__device__ float g_rsum[BATCH*CCH*HH], g_rmax[BATCH*CCH*HH];
__device__ float g_csum[BATCH*HH*WW],  g_cmax[BATCH*HH*WW];
__device__ float g_m1avg[BATCH*CCH], g_m1max[BATCH*CCH];
__device__ float g_m2avg[BATCH*WW], g_m2max[BATCH*WW];
__device__ float g_m3avg[BATCH*HH], g_m3max[BATCH*HH];
__device__ float g_coef[36];
__device__ float g_U1[BATCH*CCH*4], g_U2[BATCH*WW*4], g_U3[BATCH*HH*4];
__device__ float g_V1[BATCH*CCH*4];
__device__ float g_gavg[BATCH*CCH], g_gmax[BATCH*CCH], g_spec[BATCH*CCH];

__device__ __forceinline__ uint32_t packbf(float a, float b) {
    __nv_bfloat162 t = __floats2bfloat162_rn(a, b);
    return *(uint32_t*)&t;
}
__device__ __forceinline__ float sigmoidf(float x) { return 1.0f/(1.0f+expf(-x)); }

// weight prep: fragment-order bf16 pairs for mma.m16n8k16.
// uint4 id = (tap, cc, t=(ks*4+mi)*4+wm, lane) -> {a0,a1,a2,a3} k-pair words
__global__ void k_prep_w(const float* __restrict__ w) {
    int id = blockIdx.x*256 + threadIdx.x;       // 0..147455
    int tap = id / 16384;
    int r = id % 16384;
    int cc = r >> 11;
    int q = r & 2047;
    int lane = q & 31, t = q >> 5;
    int wm = t & 3, mi = (t>>2)&3, ks = t>>4;
    int g = lane>>2, tg = lane&3;
    int o  = wm*64 + mi*16 + g;
    int k0 = cc*64 + ks*16 + 2*tg;
    int kh = tap/3, kw = tap - kh*3;
    const float* wb = w + (size_t)kh*3 + kw;
    auto W = [&](int oo, int kk){ return wb[((size_t)oo*CIN + kk)*9]; };
    uint4 v;
    v.x = packbf(W(o,  k0  ), W(o,  k0+1));
    v.y = packbf(W(o+8,k0  ), W(o+8,k0+1));
    v.z = packbf(W(o,  k0+8), W(o,  k0+9));
    v.w = packbf(W(o+8,k0+8), W(o+8,k0+9));
    g_Wp4[id] = v;
}

// input prep: g_Xp[b][kp][h][w] = (bf16(x[2kp][h][w]), bf16(x[2kp+1][h][w]))
__global__ void k_prep_x(const float* __restrict__ frm, const float* __restrict__ oth) {
    int id = blockIdx.x*256 + threadIdx.x;       // 0..8388607 (uint4 units)
    int w4 = id & 31, h = (id>>5)&127, kp = (id>>12)&255, b = id>>20;
    int ci0 = 2*kp;
    const float* p0 = (ci0 < 256) ? (frm + (((size_t)(b*256+ci0)    *HH + h)*WW))
                                  : (oth + (((size_t)(b*256+ci0-256)*HH + h)*WW));
    const float* p1 = (ci0+1 < 256) ? (frm + (((size_t)(b*256+ci0+1)    *HH + h)*WW))
                                    : (oth + (((size_t)(b*256+ci0+1-256)*HH + h)*WW));
    float4 A = *(const float4*)(p0 + w4*4);
    float4 B = *(const float4*)(p1 + w4*4);
    uint4 v;
    v.x = packbf(A.x, B.x); v.y = packbf(A.y, B.y);
    v.z = packbf(A.z, B.z); v.w = packbf(A.w, B.w);
    ((uint4*)g_Xp)[id] = v;
}

// fold adapter+U_gen: logits_k = wA[k]*avg + wM[k]*mx + c0[k]
__global__ void k_coef(const float* a1w, const float* a1b, const float* a2w, const float* a2b,
                       const float* a3w, const float* a3b, const float* ugw, const float* ugb) {
    int j = threadIdx.x;
    if (j >= 36) return;
    const float* aw[3] = { a1w, a2w, a3w };
    const float* ab[3] = { a1b, a2b, a3b };
    int m = j/12, r = (j%12)/4, k = j%4;
    float s = 0.f;
    if (r == 0)      { for (int c=0;c<CCH;c++) s += ugw[k*CCH+c]*aw[m][c*2]; }
    else if (r == 1) { for (int c=0;c<CCH;c++) s += ugw[k*CCH+c]*aw[m][c*2+1]; }
    else             { for (int c=0;c<CCH;c++) s += ugw[k*CCH+c]*ab[m][c]; s += ugb[k]; }
    g_coef[j] = s;
}

// conv3x3 SAME + bias + LeakyReLU via mma.sync bf16 m16n8k16, cp.async staging,
// 512 threads (16 warps: wm over 4x64 co, wn over 4x32 w), KC=64, 72 stages,
// fused deterministic mode reductions. block=(h,b). No Fm materialization.
__global__ void __launch_bounds__(512, 1)
k_conv(const float* __restrict__ bias) {
    extern __shared__ float smem[];
    float*     As = smem;                           // 2 x 8192 floats (uint4 frags)
    uint32_t*  Bs = (uint32_t*)(smem + 2*A_STAGE_F);// 2 x [32][136] u32 kp-pair words
    uint32_t smemb = (uint32_t)__cvta_generic_to_shared(smem);
    const uint32_t AsB = smemb;
    const uint32_t BsB = smemb + 2*A_STAGE_F*4;

    const int h = blockIdx.x, b = blockIdx.y;
    const int tid = threadIdx.x, warp = tid>>5, lane = tid&31;
    const int g = lane>>2, tg = lane&3;
    const int wm = warp&3, wn = warp>>2;

    float acc[4][4][4];
#pragma unroll
    for (int i=0;i<4;i++)
#pragma unroll
    for (int j=0;j<4;j++)
#pragma unroll
    for (int q=0;q<4;q++) acc[i][j][q]=0.f;

    auto issueA = [&](int tap, int cc, int buf) {
        const char* src = (const char*)(g_Wp4 + (size_t)(tap*8 + cc)*2048);
        uint32_t dst = AsB + (uint32_t)buf*A_STAGE_F*4;
#pragma unroll
        for (int j=0;j<4;j++) {
            int idx = j*512 + tid;
            asm volatile("cp.async.cg.shared.global [%0], [%1], 16;"
                         :: "r"(dst + idx*16), "l"(src + (size_t)idx*16));
        }
    };
    auto issueB = [&](int r, int cc, int buf) {
        uint32_t dstb = BsB + (uint32_t)buf*(B_STAGE_W*4);
        int rc = (r < 0) ? 0 : (r >= HH ? HH-1 : r);
        int ok = (r >= 0 && r < HH) ? 16 : 0;
#pragma unroll
        for (int j=0;j<2;j++) {
            int id = j*512 + tid;
            int row = id>>5, cw = id&31;
            int kp = cc*32 + row;
            const uint32_t* src = g_Xp + ((size_t)(b*256+kp)*HH + rc)*WW + cw*4;
            uint32_t dst = dstb + (uint32_t)(row*BSTRIDE + 4 + cw*4)*4;
            asm volatile("cp.async.cg.shared.global [%0], [%1], 16, %2;"
                         :: "r"(dst), "l"(src), "r"(ok));
        }
    };

    // zero halo words (u32 cols 3 and 132), issue stage 0
    if (tid < 64) {
        int buf = tid>>5, row = tid&31;
        Bs[buf*B_STAGE_W + row*BSTRIDE + 3]   = 0u;
        Bs[buf*B_STAGE_W + row*BSTRIDE + 132] = 0u;
    }
    issueA(0, 0, 0);
    issueB(h-1, 0, 0);
    asm volatile("cp.async.commit_group;");

    for (int s=0; s<72; s++) {
        asm volatile("cp.async.wait_group 0;");
        __syncthreads();
        int nxt = s+1;
        if (nxt < 72) {
            int ndy = nxt/24, nrem = nxt%24, ncc = nrem/3, ndx = nrem%3;
            issueA(ndy*3 + ndx, ncc, nxt&1);
            if (ndx == 0) issueB(h + ndy - 1, ncc, (nxt/3)&1);
            asm volatile("cp.async.commit_group;");
        }
        const int dx = s%3;
        const uint4*    Af = (const uint4*)(As + (s&1)*A_STAGE_F);
        const uint32_t* Bu = Bs + ((s/3)&1)*B_STAGE_W;

#pragma unroll
        for (int ks=0; ks<4; ks++) {
            uint4 af[4]; uint32_t bf[4][2];
#pragma unroll
            for (int mi=0; mi<4; mi++)
                af[mi] = Af[((ks*4+mi)*4 + wm)*32 + lane];
#pragma unroll
            for (int ni=0; ni<4; ni++) {
                int col = 3 + wn*32 + ni*8 + g + dx;
                bf[ni][0] = Bu[(ks*8 + tg    )*BSTRIDE + col];
                bf[ni][1] = Bu[(ks*8 + tg + 4)*BSTRIDE + col];
            }
#pragma unroll
            for (int mi=0; mi<4; mi++)
#pragma unroll
            for (int ni=0; ni<4; ni++) {
                asm volatile(
                    "mma.sync.aligned.m16n8k16.row.col.f32.bf16.bf16.f32 "
                    "{%0,%1,%2,%3}, {%4,%5,%6,%7}, {%8,%9}, {%0,%1,%2,%3};\n"
                    : "+f"(acc[mi][ni][0]), "+f"(acc[mi][ni][1]),
                      "+f"(acc[mi][ni][2]), "+f"(acc[mi][ni][3])
                    : "r"(af[mi].x), "r"(af[mi].y), "r"(af[mi].z), "r"(af[mi].w),
                      "r"(bf[ni][0]), "r"(bf[ni][1]));
            }
        }
    }

    // ---- fused epilogue: bias + LeakyReLU + deterministic mode reductions ----
    float* sR = smem;             // [4][256] row sums (per wn quarter)
    float* mR = smem + 1024;      // [4][256] row maxes
    float* sC = smem + 2048;      // [4][128] col sums (per wm quarter)
    float* mC = smem + 2560;      // [4][128] col maxes
    __syncthreads();

    float caS[4], caM[4], cbS[4], cbM[4];
#pragma unroll
    for (int ni=0;ni<4;ni++){ caS[ni]=0.f; cbS[ni]=0.f; caM[ni]=-3.0e38f; cbM[ni]=-3.0e38f; }

#pragma unroll
    for (int mi=0; mi<4; mi++) {
        int m0 = wm*64 + mi*16 + g;
        float b0v = bias[m0], b1v = bias[m0+8];
        float rs0=0.f, rs1=0.f, rm0=-3.0e38f, rm1=-3.0e38f;
#pragma unroll
        for (int ni=0; ni<4; ni++) {
            float v0 = acc[mi][ni][0] + b0v; v0 = (v0>=0.f)?v0:0.01f*v0;
            float v1 = acc[mi][ni][1] + b0v; v1 = (v1>=0.f)?v1:0.01f*v1;
            float v2 = acc[mi][ni][2] + b1v; v2 = (v2>=0.f)?v2:0.01f*v2;
            float v3 = acc[mi][ni][3] + b1v; v3 = (v3>=0.f)?v3:0.01f*v3;
            rs0 += v0+v1; rm0 = fmaxf(rm0, fmaxf(v0,v1));
            rs1 += v2+v3; rm1 = fmaxf(rm1, fmaxf(v2,v3));
            caS[ni] += v0+v2; caM[ni] = fmaxf(caM[ni], fmaxf(v0,v2));
            cbS[ni] += v1+v3; cbM[ni] = fmaxf(cbM[ni], fmaxf(v1,v3));
        }
        rs0 += __shfl_xor_sync(0xffffffffu, rs0, 1); rs0 += __shfl_xor_sync(0xffffffffu, rs0, 2);
        rs1 += __shfl_xor_sync(0xffffffffu, rs1, 1); rs1 += __shfl_xor_sync(0xffffffffu, rs1, 2);
        rm0 = fmaxf(rm0, __shfl_xor_sync(0xffffffffu, rm0, 1));
        rm0 = fmaxf(rm0, __shfl_xor_sync(0xffffffffu, rm0, 2));
        rm1 = fmaxf(rm1, __shfl_xor_sync(0xffffffffu, rm1, 1));
        rm1 = fmaxf(rm1, __shfl_xor_sync(0xffffffffu, rm1, 2));
        if (tg == 0) {
            sR[wn*256 + m0]   = rs0; mR[wn*256 + m0]   = rm0;
            sR[wn*256 + m0+8] = rs1; mR[wn*256 + m0+8] = rm1;
        }
    }
#pragma unroll
    for (int ni=0; ni<4; ni++) {
        caS[ni] += __shfl_xor_sync(0xffffffffu, caS[ni], 4);
        caS[ni] += __shfl_xor_sync(0xffffffffu, caS[ni], 8);
        caS[ni] += __shfl_xor_sync(0xffffffffu, caS[ni], 16);
        cbS[ni] += __shfl_xor_sync(0xffffffffu, cbS[ni], 4);
        cbS[ni] += __shfl_xor_sync(0xffffffffu, cbS[ni], 8);
        cbS[ni] += __shfl_xor_sync(0xffffffffu, cbS[ni], 16);
        caM[ni] = fmaxf(caM[ni], __shfl_xor_sync(0xffffffffu, caM[ni], 4));
        caM[ni] = fmaxf(caM[ni], __shfl_xor_sync(0xffffffffu, caM[ni], 8));
        caM[ni] = fmaxf(caM[ni], __shfl_xor_sync(0xffffffffu, caM[ni], 16));
        cbM[ni] = fmaxf(cbM[ni], __shfl_xor_sync(0xffffffffu, cbM[ni], 4));
        cbM[ni] = fmaxf(cbM[ni], __shfl_xor_sync(0xffffffffu, cbM[ni], 8));
        cbM[ni] = fmaxf(cbM[ni], __shfl_xor_sync(0xffffffffu, cbM[ni], 16));
        if (g == 0) {
            int w0 = wn*32 + ni*8 + tg*2;
            sC[wm*128 + w0]   = caS[ni]; mC[wm*128 + w0]   = caM[ni];
            sC[wm*128 + w0+1] = cbS[ni]; mC[wm*128 + w0+1] = cbM[ni];
        }
    }
    __syncthreads();
    if (tid < 256) {        // row stats: c = tid
        float s = sR[tid] + sR[256+tid] + sR[512+tid] + sR[768+tid];
        float m = fmaxf(fmaxf(mR[tid], mR[256+tid]), fmaxf(mR[512+tid], mR[768+tid]));
        g_rsum[(size_t)(b*CCH+tid)*HH + h] = s;
        g_rmax[(size_t)(b*CCH+tid)*HH + h] = m;
    } else if (tid < 384) { // col stats: w = tid-256
        int w = tid - 256;
        float s = sC[w] + sC[128+w] + sC[256+w] + sC[384+w];
        float m = fmaxf(fmaxf(mC[w], mC[128+w]), fmaxf(mC[256+w], mC[384+w]));
        g_csum[(size_t)(b*HH+h)*WW + w] = s;
        g_cmax[(size_t)(b*HH+h)*WW + w] = m;
    }
}

// fold partials into the six mode vectors (deterministic)
__global__ void k_stats() {
    int id = blockIdx.x*256 + threadIdx.x;    // 0..4095
    if (id < 2048) {                          // m1: per (b,c) over (h,w)
        const float* ps = g_rsum + (size_t)id*HH;
        const float* pm = g_rmax + (size_t)id*HH;
        float s=0.f, m=-3.0e38f;
        for (int h=0;h<HH;h++) { s += ps[h]; m = fmaxf(m, pm[h]); }
        g_m1avg[id] = s*(1.0f/16384.0f); g_m1max[id] = m;
    } else if (id < 3072) {                   // m2: per (b,w) over (c,h)
        int i = id-2048, b = i>>7, w = i&127;
        float s=0.f, m=-3.0e38f;
        for (int h=0;h<HH;h++) {
            s += g_csum[(size_t)(b*HH+h)*WW + w];
            m = fmaxf(m, g_cmax[(size_t)(b*HH+h)*WW + w]);
        }
        g_m2avg[i] = s*(1.0f/32768.0f); g_m2max[i] = m;
    } else {                                  // m3: per (b,h) over (c,w)
        int i = id-3072, b = i>>7, h = i&127;
        float s=0.f, m=-3.0e38f;
        for (int c=0;c<CCH;c++) {
            s += g_rsum[(size_t)(b*CCH+c)*HH + h];
            m = fmaxf(m, g_rmax[(size_t)(b*CCH+c)*HH + h]);
        }
        g_m3avg[i] = s*(1.0f/32768.0f); g_m3max[i] = m;
    }
}

__global__ void k_U() {
    int id = blockIdx.x*256 + threadIdx.x;   // 0..4095
    float avg, mx; float* out; int m;
    if (id < 2048)      { avg=g_m1avg[id];      mx=g_m1max[id];      out=g_U1+id*4;   m=0; }
    else if (id < 3072) { int i=id-2048; avg=g_m2avg[i]; mx=g_m2max[i]; out=g_U2+i*4; m=1; }
    else                { int i=id-3072; avg=g_m3avg[i]; mx=g_m3max[i]; out=g_U3+i*4; m=2; }
    float lg[4], mxl = -3.0e38f;
#pragma unroll
    for (int k=0;k<4;k++) {
        lg[k] = g_coef[m*12+k]*avg + g_coef[m*12+4+k]*mx + g_coef[m*12+8+k];
        mxl = fmaxf(mxl, lg[k]);
    }
    float s = 0.f;
#pragma unroll
    for (int k=0;k<4;k++) { lg[k] = expf(lg[k]-mxl); s += lg[k]; }
    float inv = 1.0f/s;
#pragma unroll
    for (int k=0;k<4;k++) out[k] = lg[k]*inv;
}

__global__ void k_V1(const float* __restrict__ rw) {
    int i = blockIdx.x*256 + threadIdx.x;    // 0..8191
    int b = i>>10, o = (i>>2)&255, k = i&3;
    float s = 0.f;
    for (int c=0;c<CCH;c++) s += rw[o*CCH+c]*g_U1[(b*CCH+c)*4+k];
    g_V1[i] = s;
}

// spectral stats: g_avg / g_max over F_spe[b,c,n] = U1 . U23
__global__ void k_spec1() {
    int b = blockIdx.x, c = threadIdx.x;
    __shared__ float su[256][4];
#pragma unroll
    for (int k=0;k<4;k++)
        su[c][k] = (c < 128) ? g_U2[(b*128+c)*4+k] : g_U3[(b*128+(c-128))*4+k];
    __syncthreads();
    float u1[4];
#pragma unroll
    for (int k=0;k<4;k++) u1[k] = g_U1[(b*CCH+c)*4+k];
    float s = 0.f, m = -3.0e38f;
    for (int n=0;n<256;n++) {
        float d = u1[0]*su[n][0]+u1[1]*su[n][1]+u1[2]*su[n][2]+u1[3]*su[n][3];
        s += d; m = fmaxf(m, d);
    }
    g_gavg[b*CCH+c] = s*(1.0f/256.0f);
    g_gmax[b*CCH+c] = m;
}

__global__ void k_spec2(const float* spa_w, const float* spa_b,
                        const float* spm_w, const float* spm_b) {
    int i = blockIdx.x*256 + threadIdx.x;    // 0..2047
    int b = i>>8, o = i&255;
    float s = spa_b[o] + spm_b[o];
    for (int c=0;c<CCH;c++)
        s += g_gavg[b*CCH+c]*spa_w[o*CCH+c] + g_gmax[b*CCH+c]*spm_w[o*CCH+c];
    g_spec[i] = sigmoidf(sigmoidf(s));
}

// final: fused = a*Watt*frm + (1-a)*(1-Watt)*oth ; cp = V1.(U2*U3) + recon_b
__global__ void __launch_bounds__(256)
k_final(const float* __restrict__ frm, const float* __restrict__ oth,
        const float* __restrict__ recon_b, const float* __restrict__ spw,
        const float* __restrict__ spb, const float* __restrict__ alpha,
        float* __restrict__ out) {
    const int h = blockIdx.x, b = blockIdx.y, tid = threadIdx.x;
    __shared__ float su2[128][4], t[256][4], sspec[256], srb[256], ssa[128];
    float u3[4];
#pragma unroll
    for (int k=0;k<4;k++) u3[k] = g_U3[(b*128+h)*4+k];
    if (tid < 128) {
#pragma unroll
        for (int k=0;k<4;k++) su2[tid][k] = g_U2[(b*128+tid)*4+k];
    }
#pragma unroll
    for (int k=0;k<4;k++) t[tid][k] = g_V1[(b*CCH+tid)*4+k]*u3[k];
    sspec[tid] = g_spec[b*CCH+tid];
    srb[tid] = recon_b[tid];
    __syncthreads();
    if (tid < 128) {
        float d = u3[0]*su2[tid][0]+u3[1]*su2[tid][1]+u3[2]*su2[tid][2]+u3[3]*su2[tid][3];
        ssa[tid] = sigmoidf(spw[0]*d + spb[0]);
    }
    __syncthreads();
    const float a = alpha[0];
    const size_t N = (size_t)BATCH*CCH*HH*WW;
    for (int it=0; it<128; it++) {
        int l = it*256 + tid;
        int c = l>>7, w = l&127;
        size_t addr = (((size_t)(b*CCH+c)*HH)+h)*WW + w;
        float f = frm[addr], o = oth[addr];
        float cp = t[c][0]*su2[w][0]+t[c][1]*su2[w][1]+t[c][2]*su2[w][2]+t[c][3]*su2[w][3] + srb[c];
        float Watt = sspec[c]*ssa[w];
        out[addr]     = a*Watt*f + (1.0f-a)*(1.0f-Watt)*o;
        out[N + addr] = cp;
    }
}

extern "C" void kernel_launch(void* const* d_in, const int* in_sizes, int n_in,
                              void* d_out, int out_size) {
    const float* frm  = (const float*)d_in[0];
    const float* oth  = (const float*)d_in[1];
    const float* cw   = (const float*)d_in[2];
    const float* cb   = (const float*)d_in[3];
    const float* a1w  = (const float*)d_in[4];
    const float* a1b  = (const float*)d_in[5];
    const float* a2w  = (const float*)d_in[6];
    const float* a2b  = (const float*)d_in[7];
    const float* a3w  = (const float*)d_in[8];
    const float* a3b  = (const float*)d_in[9];
    const float* ugw  = (const float*)d_in[10];
    const float* ugb  = (const float*)d_in[11];
    const float* rw   = (const float*)d_in[12];
    const float* rb   = (const float*)d_in[13];
    const float* spw  = (const float*)d_in[14];
    const float* spb  = (const float*)d_in[15];
    const float* spaw = (const float*)d_in[16];
    const float* spab = (const float*)d_in[17];
    const float* spmw = (const float*)d_in[18];
    const float* spmb = (const float*)d_in[19];
    const float* alph = (const float*)d_in[20];
    float* out = (float*)d_out;

    cudaFuncSetAttribute(k_conv, cudaFuncAttributeMaxDynamicSharedMemorySize, SMEM_BYTES);

    k_prep_w<<<576, 256>>>(cw);
    k_prep_x<<<32768, 256>>>(frm, oth);
    k_coef<<<1, 64>>>(a1w, a1b, a2w, a2b, a3w, a3b, ugw, ugb);
    k_conv<<<dim3(HH, BATCH), 512, SMEM_BYTES>>>(cb);
    k_stats<<<16, 256>>>();
    k_U<<<16, 256>>>();
    k_V1<<<32, 256>>>(rw);
    k_spec1<<<BATCH, 256>>>();
    k_spec2<<<8, 256>>>(spaw, spab, spmw, spmb);
    k_final<<<dim3(HH, BATCH), 256>>>(frm, oth, rb, spw, spb, alph, out);
}